// round 10
// baseline (speedup 1.0000x reference)
#include <cuda_runtime.h>
#include <cuda_bf16.h>
#include <math.h>
#include <stdint.h>

#define N_TOK 4096
#define D     320
#define HEADS 8
#define DH    40
#define CTX_N 77
#define CTX_M 96
#define CTX_D 768
#define FFI   1280
#define GROUPS 32
#define LOG2E 1.4426950408889634f

typedef __nv_bfloat16 bf16;

// ---------------- scratch ----------------
__device__ float g_h  [N_TOK * D];
__device__ float g_h2 [N_TOK * D];
__device__ float g_kvc[CTX_M * 2 * D];
__device__ float g_mu [GROUPS];
__device__ float g_rs [GROUPS];

__device__ bf16 g_lnb [N_TOK * D];
__device__ bf16 g_qkvb[N_TOK * 3 * D];
__device__ bf16 g_attnb[N_TOK * D];
__device__ bf16 g_q2b [N_TOK * D];
__device__ bf16 g_h2b [N_TOK * D];
__device__ bf16 g_ffgb[N_TOK * FFI];
__device__ bf16 g_ctxb[CTX_M * CTX_D];

// weights, bf16, stored as B^T = [N][K]
__device__ bf16 g_wqkv[3 * D * D];
__device__ bf16 g_wo1 [D * D];
__device__ bf16 g_wq2 [D * D];
__device__ bf16 g_wo2 [D * D];
__device__ bf16 g_wff1[2 * FFI * D];     // INTERLEAVED: row 2c = a_c, row 2c+1 = g_c
__device__ bf16 g_wff2[D * FFI];
__device__ bf16 g_wpin[D * D];
__device__ bf16 g_wpout[D * D];
__device__ bf16 g_wkv2[2 * D * CTX_D];   // rows 0-319 = k2^T, 320-639 = v2^T

// ---------------- helpers ----------------
__device__ __forceinline__ uint32_t bf2pk(float lo, float hi) {
    uint32_t r;
    asm("cvt.rn.bf16x2.f32 %0, %1, %2;" : "=r"(r) : "f"(hi), "f"(lo));
    return r;
}
__device__ __forceinline__ void mma_bf16(float* c, const uint32_t* a, const uint32_t* b) {
    asm volatile(
        "mma.sync.aligned.m16n8k16.row.col.f32.bf16.bf16.f32 "
        "{%0,%1,%2,%3}, {%4,%5,%6,%7}, {%8,%9}, {%0,%1,%2,%3};"
        : "+f"(c[0]), "+f"(c[1]), "+f"(c[2]), "+f"(c[3])
        : "r"(a[0]), "r"(a[1]), "r"(a[2]), "r"(a[3]), "r"(b[0]), "r"(b[1]));
}
__device__ __forceinline__ void mma_bf16_k8(float* c, const uint32_t* a, uint32_t b) {
    asm volatile(
        "mma.sync.aligned.m16n8k8.row.col.f32.bf16.bf16.f32 "
        "{%0,%1,%2,%3}, {%4,%5}, {%6}, {%0,%1,%2,%3};"
        : "+f"(c[0]), "+f"(c[1]), "+f"(c[2]), "+f"(c[3])
        : "r"(a[0]), "r"(a[1]), "r"(b));
}
__device__ __forceinline__ uint32_t smem_u32(const void* p) {
    return (uint32_t)__cvta_generic_to_shared(p);
}
__device__ __forceinline__ void cp16(uint32_t dst, const void* src) {
    asm volatile("cp.async.cg.shared.global [%0], [%1], 16;" :: "r"(dst), "l"(src));
}
__device__ __forceinline__ void cp8(uint32_t dst, const void* src) {
    asm volatile("cp.async.ca.shared.global [%0], [%1], 8;" :: "r"(dst), "l"(src));
}
#define CP_COMMIT() asm volatile("cp.async.commit_group;")
#define CP_WAIT1()  asm volatile("cp.async.wait_group 1;")
#define CP_WAIT0()  asm volatile("cp.async.wait_group 0;")

__device__ __forceinline__ float gelu_exact(float g) {
    return 0.5f * g * (1.f + erff(g * 0.70710678118654752f));
}
__device__ __forceinline__ void ldmatrix_x2_trans(uint32_t& d0, uint32_t& d1, uint32_t addr) {
    asm volatile("ldmatrix.sync.aligned.m8n8.x2.trans.shared.b16 {%0,%1}, [%2];"
                 : "=r"(d0), "=r"(d1) : "r"(addr));
}
__device__ __forceinline__ void ldmatrix_x4(uint32_t& d0, uint32_t& d1, uint32_t& d2,
                                            uint32_t& d3, uint32_t addr) {
    asm volatile("ldmatrix.sync.aligned.m8n8.x4.shared.b16 {%0,%1,%2,%3}, [%4];"
                 : "=r"(d0), "=r"(d1), "=r"(d2), "=r"(d3) : "r"(addr));
}

// ---------------- weight prep (+ ctx conversion fused) ------------------------------
__global__ void __launch_bounds__(256) prep_weights_kernel(
    const float* __restrict__ q1, const float* __restrict__ k1, const float* __restrict__ v1,
    const float* __restrict__ o1, const float* __restrict__ q2, const float* __restrict__ o2,
    const float* __restrict__ ff1, const float* __restrict__ ff2,
    const float* __restrict__ pin, const float* __restrict__ pout,
    const float* __restrict__ k2, const float* __restrict__ v2,
    const float* __restrict__ ctx)
{
    int b = blockIdx.x;
    int tx = threadIdx.x & 31, ty = threadIdx.x >> 5;   // 32 x 8
    if (b < 2280) {
        __shared__ float sm[32][33];
        const float* src; bf16* dst; int R, C, tile; bool ileave = false;
        if (b < 100)       { src = q1;  dst = g_wqkv;            R = 320;  C = 320;  tile = b; }
        else if (b < 200)  { src = k1;  dst = g_wqkv + 320*320;  R = 320;  C = 320;  tile = b - 100; }
        else if (b < 300)  { src = v1;  dst = g_wqkv + 640*320;  R = 320;  C = 320;  tile = b - 200; }
        else if (b < 400)  { src = o1;  dst = g_wo1;             R = 320;  C = 320;  tile = b - 300; }
        else if (b < 500)  { src = q2;  dst = g_wq2;             R = 320;  C = 320;  tile = b - 400; }
        else if (b < 600)  { src = o2;  dst = g_wo2;             R = 320;  C = 320;  tile = b - 500; }
        else if (b < 1400) { src = ff1; dst = g_wff1;            R = 320;  C = 2560; tile = b - 600; ileave = true; }
        else if (b < 1800) { src = ff2; dst = g_wff2;            R = 1280; C = 320;  tile = b - 1400; }
        else if (b < 2040) { src = k2;  dst = g_wkv2;            R = 768;  C = 320;  tile = b - 1800; }
        else               { src = v2;  dst = g_wkv2 + 320*768;  R = 768;  C = 320;  tile = b - 2040; }
        int tc = C / 32;
        int r0 = (tile / tc) * 32, c0 = (tile % tc) * 32;
        #pragma unroll
        for (int i = 0; i < 4; i++)
            sm[ty + 8 * i][tx] = src[(size_t)(r0 + ty + 8 * i) * C + c0 + tx];
        __syncthreads();
        #pragma unroll
        for (int i = 0; i < 4; i++) {
            int sc = c0 + ty + 8 * i;
            int dr = ileave ? ((sc < FFI) ? 2 * sc : 2 * (sc - FFI) + 1) : sc;
            dst[(size_t)dr * R + r0 + tx] = __float2bfloat16(sm[tx][ty + 8 * i]);
        }
    } else if (b < 2480) {
        const float* src = (b < 2380) ? pin : pout;
        bf16* dst = (b < 2380) ? g_wpin : g_wpout;
        int seg = b - ((b < 2380) ? 2280 : 2380);
        int base = seg * 1024 + threadIdx.x * 4;
        #pragma unroll
        for (int j = 0; j < 4; j++)
            dst[base + j] = __float2bfloat16(src[base + j]);
    } else {
        int i = (b - 2480) * 256 + threadIdx.x;     // over 96*768
        int r = i / CTX_D;
        float v = (r < CTX_N) ? ctx[(size_t)r * CTX_D + (i % CTX_D)] : 0.f;
        g_ctxb[i] = __float2bfloat16(v);
    }
}

// ---------------- GroupNorm stats (float4) ----------------
__global__ void gn_stats_kernel(const float* __restrict__ x) {
    int g = blockIdx.x;
    const float4* p = (const float4*)(x + g * (10 * N_TOK));
    float s = 0.f, s2 = 0.f;
    for (int i = threadIdx.x; i < 10 * N_TOK / 4; i += 256) {
        float4 v = p[i];
        s  += v.x + v.y + v.z + v.w;
        s2 += v.x * v.x + v.y * v.y + v.z * v.z + v.w * v.w;
    }
    __shared__ float sh1[8], sh2[8];
    int lane = threadIdx.x & 31, w = threadIdx.x >> 5;
    #pragma unroll
    for (int o = 16; o; o >>= 1) {
        s  += __shfl_xor_sync(0xffffffffu, s,  o);
        s2 += __shfl_xor_sync(0xffffffffu, s2, o);
    }
    if (lane == 0) { sh1[w] = s; sh2[w] = s2; }
    __syncthreads();
    if (threadIdx.x == 0) {
        s = 0.f; s2 = 0.f;
        #pragma unroll
        for (int i = 0; i < 8; i++) { s += sh1[i]; s2 += sh2[i]; }
        float m   = s  * (1.f / (10 * N_TOK));
        float var = s2 * (1.f / (10 * N_TOK)) - m * m;
        g_mu[g] = m;
        g_rs[g] = rsqrtf(var + 1e-6f);
    }
}

// ---------------- GN apply + transpose -> bf16 token-major (vectorized) -------------
__global__ void __launch_bounds__(256) gn_apply_t_kernel(
    const float* __restrict__ x, const float* __restrict__ w,
    const float* __restrict__ b, bf16* __restrict__ out)
{
    __shared__ float sm[32][133];
    int p0 = blockIdx.x * 128, c0 = blockIdx.y * 32;
    int tx = threadIdx.x & 31, ty = threadIdx.x >> 5;
    #pragma unroll
    for (int i = 0; i < 4; i++) {
        int c = c0 + ty + 8 * i;
        float4 v = *(const float4*)(x + (size_t)c * N_TOK + p0 + tx * 4);
        sm[ty + 8 * i][tx * 4 + 0] = v.x;
        sm[ty + 8 * i][tx * 4 + 1] = v.y;
        sm[ty + 8 * i][tx * 4 + 2] = v.z;
        sm[ty + 8 * i][tx * 4 + 3] = v.w;
    }
    __syncthreads();
    int txc = threadIdx.x & 7, typ = threadIdx.x >> 3;
    int cb = c0 + txc * 4;
    float w0 = w[cb], w1 = w[cb + 1], w2 = w[cb + 2], w3 = w[cb + 3];
    float b0 = b[cb], b1 = b[cb + 1], b2 = b[cb + 2], b3 = b[cb + 3];
    float mu0 = g_mu[cb / 10],  rs0 = g_rs[cb / 10];
    float mu1 = g_mu[(cb+1)/10], rs1 = g_rs[(cb+1)/10];
    float mu2 = g_mu[(cb+2)/10], rs2 = g_rs[(cb+2)/10];
    float mu3 = g_mu[(cb+3)/10], rs3 = g_rs[(cb+3)/10];
    #pragma unroll
    for (int i = 0; i < 4; i++) {
        int pl = typ + 32 * i;
        float v0 = (sm[txc * 4 + 0][pl] - mu0) * rs0 * w0 + b0;
        float v1 = (sm[txc * 4 + 1][pl] - mu1) * rs1 * w1 + b1;
        float v2 = (sm[txc * 4 + 2][pl] - mu2) * rs2 * w2 + b2;
        float v3 = (sm[txc * 4 + 3][pl] - mu3) * rs3 * w3 + b3;
        uint2 pk = make_uint2(bf2pk(v0, v1), bf2pk(v2, v3));
        *(uint2*)(out + (size_t)(p0 + pl) * D + cb) = pk;
    }
}

// ---------------- LayerNorm: 1 warp per row, no smem, no barriers -------------------
// grid 512, 256 threads (8 warps)
__global__ void __launch_bounds__(256) layernorm_kernel(
    const float* __restrict__ in, const float* __restrict__ w,
    const float* __restrict__ b, bf16* __restrict__ out)
{
    int wid = threadIdx.x >> 5, lane = threadIdx.x & 31;
    int row = blockIdx.x * 8 + wid;
    const float* p = in + (size_t)row * D;
    float v[10];
    float s = 0.f, s2 = 0.f;
    #pragma unroll
    for (int i = 0; i < 10; i++) {
        v[i] = p[lane + 32 * i];
        s += v[i]; s2 += v[i] * v[i];
    }
    #pragma unroll
    for (int o = 16; o; o >>= 1) {
        s  += __shfl_xor_sync(0xffffffffu, s,  o);
        s2 += __shfl_xor_sync(0xffffffffu, s2, o);
    }
    float m = s * (1.f / D);
    float var = s2 * (1.f / D) - m * m;
    float r = rsqrtf(var + 1e-5f);
    bf16* o = out + (size_t)row * D;
    #pragma unroll
    for (int i = 0; i < 10; i++) {
        int c = lane + 32 * i;
        o[c] = __float2bfloat16((v[i] - m) * r * w[c] + b[c]);
    }
}

// ---------------- bf16 NT GEMM, cp.async 3-stage, K-chunk 64, ldmatrix --------------
// tile 32x64, 128 threads (warps 2x2, warp tile 16x32); K % 64 == 0
template <int EPI>
__global__ void __launch_bounds__(128) gemm_bf16_kernel(
    const bf16* __restrict__ A, const bf16* __restrict__ Bt,
    const float* __restrict__ bias, const float* __restrict__ R,
    float* __restrict__ C, bf16* __restrict__ Cb, int M, int N, int K)
{
    __shared__ __align__(16) bf16 As[3][32][72];
    __shared__ __align__(16) bf16 Bs[3][64][72];
    int tid = threadIdx.x;
    int lane = tid & 31, wid = tid >> 5;
    int wm = wid & 1, wn = wid >> 1;
    int g = lane >> 2, t = lane & 3;
    int bm = blockIdx.y * 32, bn = blockIdx.x * 64;

    float acc[4][4];
    #pragma unroll
    for (int nf = 0; nf < 4; nf++)
        #pragma unroll
        for (int r = 0; r < 4; r++) acc[nf][r] = 0.f;

    int ar = tid >> 2, ac = (tid & 3) * 16;   // A: 32 rows x 4 chunks of 16 elems
    int br = tid >> 1, bc = (tid & 1) * 32;   // B: 64 rows x 2 chunks of 32 elems
    const bf16* Abase = A  + (size_t)(bm + ar) * K + ac;
    const bf16* Bbase = Bt + (size_t)(bn + br) * K + bc;
    uint32_t sA = smem_u32(&As[0][ar][ac]);
    uint32_t sB = smem_u32(&Bs[0][br][bc]);
    uint32_t sA0 = smem_u32(&As[0][0][0]);
    uint32_t sB0 = smem_u32(&Bs[0][0][0]);
    const int ASS = 32 * 72 * 2, BSS = 64 * 72 * 2;

    // ldmatrix lane address bases (bytes); row stride 144 B
    uint32_t aBase = sA0 + (uint32_t)((wm * 16 + (lane & 15)) * 72 + (lane >> 4) * 8) * 2;
    uint32_t bBase = sB0 + (uint32_t)((wn * 32 + (lane & 7) + ((lane & 16) ? 8 : 0)) * 72
                                      + ((lane & 8) ? 8 : 0)) * 2;

    int nt = K / 64;
    #pragma unroll
    for (int s = 0; s < 2; s++) {
        cp16(sA + s * ASS,      Abase + s * 64);
        cp16(sA + s * ASS + 16, Abase + s * 64 + 8);
        #pragma unroll
        for (int j = 0; j < 4; j++)
            cp16(sB + s * BSS + j * 16, Bbase + s * 64 + j * 8);
        CP_COMMIT();
    }

    for (int i = 0; i < nt; i++) {
        if (i + 1 < nt) { CP_WAIT1(); } else { CP_WAIT0(); }
        __syncthreads();
        if (i + 2 < nt) {
            int s = (i + 2) % 3;
            cp16(sA + s * ASS,      Abase + (i + 2) * 64);
            cp16(sA + s * ASS + 16, Abase + (i + 2) * 64 + 8);
            #pragma unroll
            for (int j = 0; j < 4; j++)
                cp16(sB + s * BSS + j * 16, Bbase + (i + 2) * 64 + j * 8);
            CP_COMMIT();
        }
        int cb = i % 3;
        uint32_t aAddr = aBase + cb * ASS;
        uint32_t bAddr = bBase + cb * BSS;
        #pragma unroll
        for (int kk = 0; kk < 4; kk++) {
            uint32_t a[4], b01[4], b23[4];
            ldmatrix_x4(a[0], a[1], a[2], a[3], aAddr + kk * 32);
            ldmatrix_x4(b01[0], b01[1], b01[2], b01[3], bAddr + kk * 32);
            ldmatrix_x4(b23[0], b23[1], b23[2], b23[3], bAddr + 2304 + kk * 32);
            mma_bf16(acc[0], a, b01 + 0);
            mma_bf16(acc[1], a, b01 + 2);
            mma_bf16(acc[2], a, b23 + 0);
            mma_bf16(acc[3], a, b23 + 2);
        }
    }

    #pragma unroll
    for (int nf = 0; nf < 4; nf++) {
        int m = bm + wm * 16 + g;
        int n = bn + wn * 32 + nf * 8 + 2 * t;
        if (EPI == 5) {
            int c2 = n >> 1;
            float ab = bias[c2], gb = bias[FFI + c2];
            float a0 = acc[nf][0] + ab, g0 = acc[nf][1] + gb;
            float a1 = acc[nf][2] + ab, g1 = acc[nf][3] + gb;
            Cb[(size_t)m * (N / 2) + c2]       = __float2bfloat16(a0 * gelu_exact(g0));
            Cb[(size_t)(m + 8) * (N / 2) + c2] = __float2bfloat16(a1 * gelu_exact(g1));
            continue;
        }
        float b0 = bias ? bias[n] : 0.f;
        float b1 = bias ? bias[n + 1] : 0.f;
        float v0 = acc[nf][0] + b0;
        float v1 = acc[nf][1] + b1;
        float v2 = acc[nf][2] + b0;
        float v3 = acc[nf][3] + b1;
        if (EPI == 2) {
            C[(size_t)n * M + m]           = v0 + R[(size_t)n * M + m];
            C[(size_t)(n + 1) * M + m]     = v1 + R[(size_t)(n + 1) * M + m];
            C[(size_t)n * M + m + 8]       = v2 + R[(size_t)n * M + m + 8];
            C[(size_t)(n + 1) * M + m + 8] = v3 + R[(size_t)(n + 1) * M + m + 8];
        } else if (EPI == 3) {
            *(uint32_t*)&Cb[(size_t)m * N + n]       = bf2pk(v0, v1);
            *(uint32_t*)&Cb[(size_t)(m + 8) * N + n] = bf2pk(v2, v3);
        } else {
            if (EPI == 1 || EPI == 4) {
                float2 r0 = *(const float2*)&R[(size_t)m * N + n];
                float2 r1 = *(const float2*)&R[(size_t)(m + 8) * N + n];
                v0 += r0.x; v1 += r0.y; v2 += r1.x; v3 += r1.y;
            }
            *(float2*)&C[(size_t)m * N + n]       = make_float2(v0, v1);
            *(float2*)&C[(size_t)(m + 8) * N + n] = make_float2(v2, v3);
            if (EPI == 4) {
                *(uint32_t*)&Cb[(size_t)m * N + n]       = bf2pk(v0, v1);
                *(uint32_t*)&Cb[(size_t)(m + 8) * N + n] = bf2pk(v2, v3);
            }
        }
    }
}

// ---------------- bf16 flash self-attention, cp.async 2-stage, ldmatrix -------------
// grid (32, 8), 256 threads = 8 warps; warp w owns query rows [w*16, w*16+16)
__global__ void __launch_bounds__(256) flash_bf16_kernel(
    const bf16* __restrict__ QKV, bf16* __restrict__ O)
{
    __shared__ __align__(16) bf16 Ks[2][64][40];
    __shared__ __align__(16) bf16 Vs[2][64][40];
    __shared__ __align__(16) bf16 Ps[128][72];
    int h = blockIdx.y;
    int q0 = blockIdx.x * 128;
    int tid = threadIdx.x, wid = tid >> 5, lane = tid & 31;
    int g = lane >> 2, t = lane & 3;
    const float sclog = 0.15811388300841897f * LOG2E;

    uint32_t ksb = smem_u32(&Ks[0][0][0]);
    uint32_t vsb = smem_u32(&Vs[0][0][0]);
    uint32_t psb = smem_u32(&Ps[0][0]);
    const int KSS = 64 * 40 * 2, VSS = 64 * 40 * 2;

    uint32_t k16Base = (uint32_t)((lane & 7) + ((lane & 16) ? 8 : 0)) * 80
                       + ((lane & 8) ? 16 : 0);
    uint32_t k8Base  = (uint32_t)lane * 80 + 64;
    uint32_t pBase   = psb + (uint32_t)(wid * 16 + (lane & 15)) * 144 + (lane >> 4) * 16;

    uint32_t qa[2][4], qa2[2];
    {
        const bf16* qb = QKV + (size_t)(q0 + wid * 16) * 960 + h * 40;
        #pragma unroll
        for (int kk = 0; kk < 2; kk++) {
            int d = kk * 16 + 2 * t;
            qa[kk][0] = *(const uint32_t*)(qb + (size_t)g * 960 + d);
            qa[kk][1] = *(const uint32_t*)(qb + (size_t)(g + 8) * 960 + d);
            qa[kk][2] = *(const uint32_t*)(qb + (size_t)g * 960 + d + 8);
            qa[kk][3] = *(const uint32_t*)(qb + (size_t)(g + 8) * 960 + d + 8);
        }
        qa2[0] = *(const uint32_t*)(qb + (size_t)g * 960 + 32 + 2 * t);
        qa2[1] = *(const uint32_t*)(qb + (size_t)(g + 8) * 960 + 32 + 2 * t);
    }

    {
        for (int idx = tid; idx < 640; idx += 256) {
            int r = idx / 10, c = (idx % 10) * 4;
            cp8(ksb + r * 80 + c * 2, QKV + (size_t)r * 960 + 320 + h * 40 + c);
            cp8(vsb + r * 80 + c * 2, QKV + (size_t)r * 960 + 640 + h * 40 + c);
        }
        CP_COMMIT();
    }

    float o[5][4];
    #pragma unroll
    for (int nf = 0; nf < 5; nf++)
        #pragma unroll
        for (int r = 0; r < 4; r++) o[nf][r] = 0.f;
    float mA = -1e30f, mB = -1e30f, lA = 0.f, lB = 0.f;

    for (int it = 0; it < 64; it++) {
        int buf = it & 1;
        if (it < 63) {
            int k0 = (it + 1) * 64;
            uint32_t kd = ksb + (buf ^ 1) * KSS;
            uint32_t vd = vsb + (buf ^ 1) * VSS;
            for (int idx = tid; idx < 640; idx += 256) {
                int r = idx / 10, c = (idx % 10) * 4;
                cp8(kd + r * 80 + c * 2, QKV + (size_t)(k0 + r) * 960 + 320 + h * 40 + c);
                cp8(vd + r * 80 + c * 2, QKV + (size_t)(k0 + r) * 960 + 640 + h * 40 + c);
            }
            CP_COMMIT();
            CP_WAIT1();
        } else {
            CP_WAIT0();
        }
        __syncthreads();

        float s[8][4];
        #pragma unroll
        for (int nf = 0; nf < 8; nf++)
            #pragma unroll
            for (int r = 0; r < 4; r++) s[nf][r] = 0.f;
        uint32_t kbuf = ksb + buf * KSS;
        #pragma unroll
        for (int kk = 0; kk < 2; kk++) {
            #pragma unroll
            for (int nfp = 0; nfp < 4; nfp++) {
                uint32_t b4[4];
                ldmatrix_x4(b4[0], b4[1], b4[2], b4[3],
                            kbuf + k16Base + nfp * 1280 + kk * 32);
                mma_bf16(s[2 * nfp],     qa[kk], b4 + 0);
                mma_bf16(s[2 * nfp + 1], qa[kk], b4 + 2);
            }
        }
        #pragma unroll
        for (int half = 0; half < 2; half++) {
            uint32_t b4[4];
            ldmatrix_x4(b4[0], b4[1], b4[2], b4[3], kbuf + k8Base + half * 2560);
            mma_bf16_k8(s[half * 4 + 0], qa2, b4[0]);
            mma_bf16_k8(s[half * 4 + 1], qa2, b4[1]);
            mma_bf16_k8(s[half * 4 + 2], qa2, b4[2]);
            mma_bf16_k8(s[half * 4 + 3], qa2, b4[3]);
        }

        float mtA = mA, mtB = mB;
        #pragma unroll
        for (int nf = 0; nf < 8; nf++) {
            mtA = fmaxf(mtA, fmaxf(s[nf][0], s[nf][1]));
            mtB = fmaxf(mtB, fmaxf(s[nf][2], s[nf][3]));
        }
        mtA = fmaxf(mtA, __shfl_xor_sync(0xffffffffu, mtA, 1));
        mtA = fmaxf(mtA, __shfl_xor_sync(0xffffffffu, mtA, 2));
        mtB = fmaxf(mtB, __shfl_xor_sync(0xffffffffu, mtB, 1));
        mtB = fmaxf(mtB, __shfl_xor_sync(0xffffffffu, mtB, 2));
        float corrA = exp2f((mA - mtA) * sclog);
        float corrB = exp2f((mB - mtB) * sclog);
        mA = mtA; mB = mtB;
        lA *= corrA; lB *= corrB;
        #pragma unroll
        for (int nf = 0; nf < 5; nf++) {
            o[nf][0] *= corrA; o[nf][1] *= corrA;
            o[nf][2] *= corrB; o[nf][3] *= corrB;
        }
        int pr = wid * 16 + g;
        #pragma unroll
        for (int nf = 0; nf < 8; nf++) {
            float p0 = exp2f((s[nf][0] - mA) * sclog);
            float p1 = exp2f((s[nf][1] - mA) * sclog);
            float p2 = exp2f((s[nf][2] - mB) * sclog);
            float p3 = exp2f((s[nf][3] - mB) * sclog);
            lA += p0 + p1; lB += p2 + p3;
            *(uint32_t*)&Ps[pr][nf * 8 + 2 * t]     = bf2pk(p0, p1);
            *(uint32_t*)&Ps[pr + 8][nf * 8 + 2 * t] = bf2pk(p2, p3);
        }
        __syncwarp();

        uint32_t vbase = vsb + buf * VSS;
        #pragma unroll
        for (int kk = 0; kk < 4; kk++) {
            uint32_t pa[4];
            ldmatrix_x4(pa[0], pa[1], pa[2], pa[3], pBase + kk * 32);
            uint32_t rowaddr = vbase + (kk * 16 + (lane & 15)) * 80;
            #pragma unroll
            for (int nf = 0; nf < 5; nf++) {
                uint32_t bb[2];
                ldmatrix_x2_trans(bb[0], bb[1], rowaddr + nf * 16);
                mma_bf16(o[nf], pa, bb);
            }
        }
        __syncthreads();
    }

    lA += __shfl_xor_sync(0xffffffffu, lA, 1);
    lA += __shfl_xor_sync(0xffffffffu, lA, 2);
    lB += __shfl_xor_sync(0xffffffffu, lB, 1);
    lB += __shfl_xor_sync(0xffffffffu, lB, 2);
    float iA = 1.f / lA, iB = 1.f / lB;
    bf16* ob = O + (size_t)(q0 + wid * 16 + g) * D + h * 40;
    #pragma unroll
    for (int nf = 0; nf < 5; nf++) {
        *(uint32_t*)(ob + nf * 8 + 2 * t) = bf2pk(o[nf][0] * iA, o[nf][1] * iA);
        *(uint32_t*)(ob + (size_t)8 * D + nf * 8 + 2 * t) = bf2pk(o[nf][2] * iB, o[nf][3] * iB);
    }
}

// ---------------- cross attention (scalar; Q bf16, 77 keys; KV merged [96][640]) ----
__global__ void __launch_bounds__(128) cross_attn_kernel(
    const bf16* __restrict__ Q, const float* __restrict__ KV, bf16* __restrict__ O)
{
    const float scale = 0.15811388300841897f;
    int h = blockIdx.y;
    int qrow = blockIdx.x * 128 + threadIdx.x;
    int tid = threadIdx.x;

    __shared__ __align__(16) float Ks[CTX_N][40];
    __shared__ __align__(16) float Vs[CTX_N][40];
    for (int i = tid; i < CTX_N * 10; i += 128) {
        int r = i / 10, c = (i % 10) * 4;
        *(float4*)&Ks[r][c] = *(const float4*)(KV + (size_t)r * 640 + h * DH + c);
        *(float4*)&Vs[r][c] = *(const float4*)(KV + (size_t)r * 640 + 320 + h * DH + c);
    }
    __syncthreads();

    float4 q4[10], a4[10];
    const bf16* qp = Q + (size_t)qrow * D + h * DH;
    #pragma unroll
    for (int dd = 0; dd < 10; dd++) {
        __nv_bfloat162 b0 = *(const __nv_bfloat162*)(qp + dd * 4);
        __nv_bfloat162 b1 = *(const __nv_bfloat162*)(qp + dd * 4 + 2);
        q4[dd] = make_float4(__low2float(b0) * scale, __high2float(b0) * scale,
                             __low2float(b1) * scale, __high2float(b1) * scale);
        a4[dd] = make_float4(0.f, 0.f, 0.f, 0.f);
    }
    float m = -1e30f, l = 0.f;
    for (int j = 0; j < CTX_N; j++) {
        float s = 0.f;
        #pragma unroll
        for (int dd = 0; dd < 10; dd++) {
            float4 kk = *(const float4*)&Ks[j][dd * 4];
            s += q4[dd].x * kk.x + q4[dd].y * kk.y + q4[dd].z * kk.z + q4[dd].w * kk.w;
        }
        float mt = fmaxf(m, s);
        float corr = __expf(m - mt);
        float p = __expf(s - mt);
        m = mt;
        l = l * corr + p;
        #pragma unroll
        for (int dd = 0; dd < 10; dd++) {
            float4 vv = *(const float4*)&Vs[j][dd * 4];
            a4[dd].x = a4[dd].x * corr + p * vv.x;
            a4[dd].y = a4[dd].y * corr + p * vv.y;
            a4[dd].z = a4[dd].z * corr + p * vv.z;
            a4[dd].w = a4[dd].w * corr + p * vv.w;
        }
    }
    float inv = 1.f / l;
    bf16* op = O + (size_t)qrow * D + h * DH;
    #pragma unroll
    for (int dd = 0; dd < 10; dd++) {
        *(uint32_t*)(op + dd * 4)     = bf2pk(a4[dd].x * inv, a4[dd].y * inv);
        *(uint32_t*)(op + dd * 4 + 2) = bf2pk(a4[dd].z * inv, a4[dd].w * inv);
    }
}

// ---------------- launch ----------------
extern "C" void kernel_launch(void* const* d_in, const int* in_sizes, int n_in,
                              void* d_out, int out_size) {
    const float* x      = (const float*)d_in[0];
    const float* ctx    = (const float*)d_in[1];
    const float* gn_w   = (const float*)d_in[2];
    const float* gn_b   = (const float*)d_in[3];
    const float* pin_w  = (const float*)d_in[4];
    const float* pin_b  = (const float*)d_in[5];
    const float* ln1_w  = (const float*)d_in[6];
    const float* ln1_b  = (const float*)d_in[7];
    const float* q1     = (const float*)d_in[8];
    const float* k1     = (const float*)d_in[9];
    const float* v1     = (const float*)d_in[10];
    const float* o1_w   = (const float*)d_in[11];
    const float* o1_b   = (const float*)d_in[12];
    const float* ln2_w  = (const float*)d_in[13];
    const float* ln2_b  = (const float*)d_in[14];
    const float* q2     = (const float*)d_in[15];
    const float* k2     = (const float*)d_in[16];
    const float* v2     = (const float*)d_in[17];
    const float* o2_w   = (const float*)d_in[18];
    const float* o2_b   = (const float*)d_in[19];
    const float* ln3_w  = (const float*)d_in[20];
    const float* ln3_b  = (const float*)d_in[21];
    const float* ff1_w  = (const float*)d_in[22];
    const float* ff1_b  = (const float*)d_in[23];
    const float* ff2_w  = (const float*)d_in[24];
    const float* ff2_b  = (const float*)d_in[25];
    const float* pout_w = (const float*)d_in[26];
    const float* pout_b = (const float*)d_in[27];
    float* out = (float*)d_out;

    float *p_h, *p_h2, *p_kvc;
    bf16 *p_lnb, *p_qkvb, *p_attnb, *p_q2b, *p_h2b, *p_ffgb, *p_ctxb;
    bf16 *p_wqkv, *p_wo1, *p_wq2, *p_wo2, *p_wff1, *p_wff2, *p_wpin, *p_wpout, *p_wkv2;
    cudaGetSymbolAddress((void**)&p_h,    g_h);
    cudaGetSymbolAddress((void**)&p_h2,   g_h2);
    cudaGetSymbolAddress((void**)&p_kvc,  g_kvc);
    cudaGetSymbolAddress((void**)&p_lnb,  g_lnb);
    cudaGetSymbolAddress((void**)&p_qkvb, g_qkvb);
    cudaGetSymbolAddress((void**)&p_attnb,g_attnb);
    cudaGetSymbolAddress((void**)&p_q2b,  g_q2b);
    cudaGetSymbolAddress((void**)&p_h2b,  g_h2b);
    cudaGetSymbolAddress((void**)&p_ffgb, g_ffgb);
    cudaGetSymbolAddress((void**)&p_ctxb, g_ctxb);
    cudaGetSymbolAddress((void**)&p_wqkv, g_wqkv);
    cudaGetSymbolAddress((void**)&p_wo1,  g_wo1);
    cudaGetSymbolAddress((void**)&p_wq2,  g_wq2);
    cudaGetSymbolAddress((void**)&p_wo2,  g_wo2);
    cudaGetSymbolAddress((void**)&p_wff1, g_wff1);
    cudaGetSymbolAddress((void**)&p_wff2, g_wff2);
    cudaGetSymbolAddress((void**)&p_wpin, g_wpin);
    cudaGetSymbolAddress((void**)&p_wpout,g_wpout);
    cudaGetSymbolAddress((void**)&p_wkv2, g_wkv2);

    dim3 gD(D / 64, N_TOK / 32);            // (5, 128)

    // weight prep (+ ctx conversion) + GroupNorm
    prep_weights_kernel<<<2768, 256>>>(q1, k1, v1, o1_w, q2, o2_w, ff1_w, ff2_w,
                                       pin_w, pout_w, k2, v2, ctx);
    gn_stats_kernel<<<GROUPS, 256>>>(x);
    gn_apply_t_kernel<<<dim3(32, 10), 256>>>(x, gn_w, gn_b, p_lnb);
    gemm_bf16_kernel<0><<<gD, 128>>>(p_lnb, p_wpin, pin_b, nullptr, p_h, nullptr, N_TOK, D, D);

    // self-attention
    layernorm_kernel<<<N_TOK / 8, 256>>>(p_h, ln1_w, ln1_b, p_lnb);
    gemm_bf16_kernel<3><<<dim3(3 * D / 64, N_TOK / 32), 128>>>(p_lnb, p_wqkv, nullptr, nullptr, nullptr, p_qkvb, N_TOK, 3 * D, D);
    flash_bf16_kernel<<<dim3(N_TOK / 128, HEADS), 256>>>(p_qkvb, p_attnb);
    gemm_bf16_kernel<1><<<gD, 128>>>(p_attnb, p_wo1, o1_b, p_h, p_h2, nullptr, N_TOK, D, D);

    // cross-attention
    layernorm_kernel<<<N_TOK / 8, 256>>>(p_h2, ln2_w, ln2_b, p_lnb);
    gemm_bf16_kernel<3><<<gD, 128>>>(p_lnb, p_wq2, nullptr, nullptr, nullptr, p_q2b, N_TOK, D, D);
    gemm_bf16_kernel<0><<<dim3(2 * D / 64, CTX_M / 32), 128>>>(p_ctxb, p_wkv2, nullptr, nullptr, p_kvc, nullptr, CTX_M, 2 * D, CTX_D);
    cross_attn_kernel<<<dim3(N_TOK / 128, HEADS), 128>>>(p_q2b, p_kvc, p_attnb);
    gemm_bf16_kernel<1><<<gD, 128>>>(p_attnb, p_wo2, o2_b, p_h2, p_h, nullptr, N_TOK, D, D);

    // GEGLU FF (fused into ff1 epilogue via interleaved weights)
    layernorm_kernel<<<N_TOK / 8, 256>>>(p_h, ln3_w, ln3_b, p_lnb);
    gemm_bf16_kernel<5><<<dim3(2 * FFI / 64, N_TOK / 32), 128>>>(p_lnb, p_wff1, ff1_b, nullptr, nullptr, p_ffgb, N_TOK, 2 * FFI, D);
    gemm_bf16_kernel<4><<<gD, 128>>>(p_ffgb, p_wff2, ff2_b, p_h, p_h2, p_h2b, N_TOK, D, FFI);

    // proj_out + residual (transposed store back to [C][HW])
    gemm_bf16_kernel<2><<<gD, 128>>>(p_h2b, p_wpout, pout_b, x, out, nullptr, N_TOK, D, D);
}

// round 11
// speedup vs baseline: 1.0582x; 1.0582x over previous
#include <cuda_runtime.h>
#include <cuda_bf16.h>
#include <math.h>
#include <stdint.h>

#define N_TOK 4096
#define D     320
#define HEADS 8
#define DH    40
#define CTX_N 77
#define CTX_M 96
#define CTX_D 768
#define FFI   1280
#define GROUPS 32
#define LOG2E 1.4426950408889634f

typedef __nv_bfloat16 bf16;

// ---------------- scratch ----------------
__device__ float g_h  [N_TOK * D];
__device__ float g_h2 [N_TOK * D];
__device__ float g_kvc[CTX_M * 2 * D];
__device__ float g_mu [GROUPS];
__device__ float g_rs [GROUPS];

__device__ bf16 g_lnb [N_TOK * D];
__device__ bf16 g_qkvb[N_TOK * 3 * D];
__device__ bf16 g_attnb[N_TOK * D];
__device__ bf16 g_q2b [N_TOK * D];
__device__ bf16 g_h2b [N_TOK * D];
__device__ bf16 g_ffgb[N_TOK * FFI];
__device__ bf16 g_ctxb[CTX_M * CTX_D];

// weights, bf16, stored as B^T = [N][K]
__device__ bf16 g_wqkv[3 * D * D];
__device__ bf16 g_wo1 [D * D];
__device__ bf16 g_wq2 [D * D];
__device__ bf16 g_wo2 [D * D];
__device__ bf16 g_wff1[2 * FFI * D];     // INTERLEAVED: row 2c = a_c, row 2c+1 = g_c
__device__ bf16 g_wff2[D * FFI];
__device__ bf16 g_wpin[D * D];
__device__ bf16 g_wpout[D * D];
__device__ bf16 g_wkv2[2 * D * CTX_D];   // rows 0-319 = k2^T, 320-639 = v2^T

// ---------------- helpers ----------------
__device__ __forceinline__ uint32_t bf2pk(float lo, float hi) {
    uint32_t r;
    asm("cvt.rn.bf16x2.f32 %0, %1, %2;" : "=r"(r) : "f"(hi), "f"(lo));
    return r;
}
__device__ __forceinline__ void mma_bf16(float* c, const uint32_t* a, const uint32_t* b) {
    asm volatile(
        "mma.sync.aligned.m16n8k16.row.col.f32.bf16.bf16.f32 "
        "{%0,%1,%2,%3}, {%4,%5,%6,%7}, {%8,%9}, {%0,%1,%2,%3};"
        : "+f"(c[0]), "+f"(c[1]), "+f"(c[2]), "+f"(c[3])
        : "r"(a[0]), "r"(a[1]), "r"(a[2]), "r"(a[3]), "r"(b[0]), "r"(b[1]));
}
__device__ __forceinline__ void mma_bf16_k8(float* c, const uint32_t* a, uint32_t b) {
    asm volatile(
        "mma.sync.aligned.m16n8k8.row.col.f32.bf16.bf16.f32 "
        "{%0,%1,%2,%3}, {%4,%5}, {%6}, {%0,%1,%2,%3};"
        : "+f"(c[0]), "+f"(c[1]), "+f"(c[2]), "+f"(c[3])
        : "r"(a[0]), "r"(a[1]), "r"(b));
}
__device__ __forceinline__ uint32_t smem_u32(const void* p) {
    return (uint32_t)__cvta_generic_to_shared(p);
}
__device__ __forceinline__ void cp16(uint32_t dst, const void* src) {
    asm volatile("cp.async.cg.shared.global [%0], [%1], 16;" :: "r"(dst), "l"(src));
}
__device__ __forceinline__ void cp8(uint32_t dst, const void* src) {
    asm volatile("cp.async.ca.shared.global [%0], [%1], 8;" :: "r"(dst), "l"(src));
}
#define CP_COMMIT() asm volatile("cp.async.commit_group;")
#define CP_WAIT1()  asm volatile("cp.async.wait_group 1;")
#define CP_WAIT0()  asm volatile("cp.async.wait_group 0;")

__device__ __forceinline__ float gelu_exact(float g) {
    return 0.5f * g * (1.f + erff(g * 0.70710678118654752f));
}
__device__ __forceinline__ void ldmatrix_x2_trans(uint32_t& d0, uint32_t& d1, uint32_t addr) {
    asm volatile("ldmatrix.sync.aligned.m8n8.x2.trans.shared.b16 {%0,%1}, [%2];"
                 : "=r"(d0), "=r"(d1) : "r"(addr));
}
__device__ __forceinline__ void ldmatrix_x4(uint32_t& d0, uint32_t& d1, uint32_t& d2,
                                            uint32_t& d3, uint32_t addr) {
    asm volatile("ldmatrix.sync.aligned.m8n8.x4.shared.b16 {%0,%1,%2,%3}, [%4];"
                 : "=r"(d0), "=r"(d1), "=r"(d2), "=r"(d3) : "r"(addr));
}

// ---------------- weight prep (+ ctx conversion fused) ------------------------------
__global__ void __launch_bounds__(256) prep_weights_kernel(
    const float* __restrict__ q1, const float* __restrict__ k1, const float* __restrict__ v1,
    const float* __restrict__ o1, const float* __restrict__ q2, const float* __restrict__ o2,
    const float* __restrict__ ff1, const float* __restrict__ ff2,
    const float* __restrict__ pin, const float* __restrict__ pout,
    const float* __restrict__ k2, const float* __restrict__ v2,
    const float* __restrict__ ctx)
{
    int b = blockIdx.x;
    int tx = threadIdx.x & 31, ty = threadIdx.x >> 5;   // 32 x 8
    if (b < 2280) {
        __shared__ float sm[32][33];
        const float* src; bf16* dst; int R, C, tile; bool ileave = false;
        if (b < 100)       { src = q1;  dst = g_wqkv;            R = 320;  C = 320;  tile = b; }
        else if (b < 200)  { src = k1;  dst = g_wqkv + 320*320;  R = 320;  C = 320;  tile = b - 100; }
        else if (b < 300)  { src = v1;  dst = g_wqkv + 640*320;  R = 320;  C = 320;  tile = b - 200; }
        else if (b < 400)  { src = o1;  dst = g_wo1;             R = 320;  C = 320;  tile = b - 300; }
        else if (b < 500)  { src = q2;  dst = g_wq2;             R = 320;  C = 320;  tile = b - 400; }
        else if (b < 600)  { src = o2;  dst = g_wo2;             R = 320;  C = 320;  tile = b - 500; }
        else if (b < 1400) { src = ff1; dst = g_wff1;            R = 320;  C = 2560; tile = b - 600; ileave = true; }
        else if (b < 1800) { src = ff2; dst = g_wff2;            R = 1280; C = 320;  tile = b - 1400; }
        else if (b < 2040) { src = k2;  dst = g_wkv2;            R = 768;  C = 320;  tile = b - 1800; }
        else               { src = v2;  dst = g_wkv2 + 320*768;  R = 768;  C = 320;  tile = b - 2040; }
        int tc = C / 32;
        int r0 = (tile / tc) * 32, c0 = (tile % tc) * 32;
        #pragma unroll
        for (int i = 0; i < 4; i++)
            sm[ty + 8 * i][tx] = src[(size_t)(r0 + ty + 8 * i) * C + c0 + tx];
        __syncthreads();
        #pragma unroll
        for (int i = 0; i < 4; i++) {
            int sc = c0 + ty + 8 * i;
            int dr = ileave ? ((sc < FFI) ? 2 * sc : 2 * (sc - FFI) + 1) : sc;
            dst[(size_t)dr * R + r0 + tx] = __float2bfloat16(sm[tx][ty + 8 * i]);
        }
    } else if (b < 2480) {
        const float* src = (b < 2380) ? pin : pout;
        bf16* dst = (b < 2380) ? g_wpin : g_wpout;
        int seg = b - ((b < 2380) ? 2280 : 2380);
        int base = seg * 1024 + threadIdx.x * 4;
        #pragma unroll
        for (int j = 0; j < 4; j++)
            dst[base + j] = __float2bfloat16(src[base + j]);
    } else {
        int i = (b - 2480) * 256 + threadIdx.x;     // over 96*768
        int r = i / CTX_D;
        float v = (r < CTX_N) ? ctx[(size_t)r * CTX_D + (i % CTX_D)] : 0.f;
        g_ctxb[i] = __float2bfloat16(v);
    }
}

// ---------------- GroupNorm stats (float4) ----------------
__global__ void gn_stats_kernel(const float* __restrict__ x) {
    int g = blockIdx.x;
    const float4* p = (const float4*)(x + g * (10 * N_TOK));
    float s = 0.f, s2 = 0.f;
    for (int i = threadIdx.x; i < 10 * N_TOK / 4; i += 256) {
        float4 v = p[i];
        s  += v.x + v.y + v.z + v.w;
        s2 += v.x * v.x + v.y * v.y + v.z * v.z + v.w * v.w;
    }
    __shared__ float sh1[8], sh2[8];
    int lane = threadIdx.x & 31, w = threadIdx.x >> 5;
    #pragma unroll
    for (int o = 16; o; o >>= 1) {
        s  += __shfl_xor_sync(0xffffffffu, s,  o);
        s2 += __shfl_xor_sync(0xffffffffu, s2, o);
    }
    if (lane == 0) { sh1[w] = s; sh2[w] = s2; }
    __syncthreads();
    if (threadIdx.x == 0) {
        s = 0.f; s2 = 0.f;
        #pragma unroll
        for (int i = 0; i < 8; i++) { s += sh1[i]; s2 += sh2[i]; }
        float m   = s  * (1.f / (10 * N_TOK));
        float var = s2 * (1.f / (10 * N_TOK)) - m * m;
        g_mu[g] = m;
        g_rs[g] = rsqrtf(var + 1e-6f);
    }
}

// ---------------- GN apply + transpose -> bf16 token-major (vectorized) -------------
__global__ void __launch_bounds__(256) gn_apply_t_kernel(
    const float* __restrict__ x, const float* __restrict__ w,
    const float* __restrict__ b, bf16* __restrict__ out)
{
    __shared__ float sm[32][133];
    int p0 = blockIdx.x * 128, c0 = blockIdx.y * 32;
    int tx = threadIdx.x & 31, ty = threadIdx.x >> 5;
    #pragma unroll
    for (int i = 0; i < 4; i++) {
        int c = c0 + ty + 8 * i;
        float4 v = *(const float4*)(x + (size_t)c * N_TOK + p0 + tx * 4);
        sm[ty + 8 * i][tx * 4 + 0] = v.x;
        sm[ty + 8 * i][tx * 4 + 1] = v.y;
        sm[ty + 8 * i][tx * 4 + 2] = v.z;
        sm[ty + 8 * i][tx * 4 + 3] = v.w;
    }
    __syncthreads();
    int txc = threadIdx.x & 7, typ = threadIdx.x >> 3;
    int cb = c0 + txc * 4;
    float w0 = w[cb], w1 = w[cb + 1], w2 = w[cb + 2], w3 = w[cb + 3];
    float b0 = b[cb], b1 = b[cb + 1], b2 = b[cb + 2], b3 = b[cb + 3];
    float mu0 = g_mu[cb / 10],  rs0 = g_rs[cb / 10];
    float mu1 = g_mu[(cb+1)/10], rs1 = g_rs[(cb+1)/10];
    float mu2 = g_mu[(cb+2)/10], rs2 = g_rs[(cb+2)/10];
    float mu3 = g_mu[(cb+3)/10], rs3 = g_rs[(cb+3)/10];
    #pragma unroll
    for (int i = 0; i < 4; i++) {
        int pl = typ + 32 * i;
        float v0 = (sm[txc * 4 + 0][pl] - mu0) * rs0 * w0 + b0;
        float v1 = (sm[txc * 4 + 1][pl] - mu1) * rs1 * w1 + b1;
        float v2 = (sm[txc * 4 + 2][pl] - mu2) * rs2 * w2 + b2;
        float v3 = (sm[txc * 4 + 3][pl] - mu3) * rs3 * w3 + b3;
        uint2 pk = make_uint2(bf2pk(v0, v1), bf2pk(v2, v3));
        *(uint2*)(out + (size_t)(p0 + pl) * D + cb) = pk;
    }
}

// ---------------- LayerNorm: 1 warp per row, no smem, no barriers -------------------
__global__ void __launch_bounds__(256) layernorm_kernel(
    const float* __restrict__ in, const float* __restrict__ w,
    const float* __restrict__ b, bf16* __restrict__ out)
{
    int wid = threadIdx.x >> 5, lane = threadIdx.x & 31;
    int row = blockIdx.x * 8 + wid;
    const float* p = in + (size_t)row * D;
    float v[10];
    float s = 0.f, s2 = 0.f;
    #pragma unroll
    for (int i = 0; i < 10; i++) {
        v[i] = p[lane + 32 * i];
        s += v[i]; s2 += v[i] * v[i];
    }
    #pragma unroll
    for (int o = 16; o; o >>= 1) {
        s  += __shfl_xor_sync(0xffffffffu, s,  o);
        s2 += __shfl_xor_sync(0xffffffffu, s2, o);
    }
    float m = s * (1.f / D);
    float var = s2 * (1.f / D) - m * m;
    float r = rsqrtf(var + 1e-5f);
    bf16* o = out + (size_t)row * D;
    #pragma unroll
    for (int i = 0; i < 10; i++) {
        int c = lane + 32 * i;
        o[c] = __float2bfloat16((v[i] - m) * r * w[c] + b[c]);
    }
}

// ---------------- bf16 NT GEMM, cp.async 3-stage, K-chunk 32, ldmatrix --------------
// tile 32x64, 128 threads (warps 2x2, warp tile 16x32)
template <int EPI>
__global__ void __launch_bounds__(128) gemm_bf16_kernel(
    const bf16* __restrict__ A, const bf16* __restrict__ Bt,
    const float* __restrict__ bias, const float* __restrict__ R,
    float* __restrict__ C, bf16* __restrict__ Cb, int M, int N, int K)
{
    __shared__ __align__(16) bf16 As[3][32][40];
    __shared__ __align__(16) bf16 Bs[3][64][40];
    int tid = threadIdx.x;
    int lane = tid & 31, wid = tid >> 5;
    int wm = wid & 1, wn = wid >> 1;
    int g = lane >> 2, t = lane & 3;
    int bm = blockIdx.y * 32, bn = blockIdx.x * 64;

    float acc[4][4];
    #pragma unroll
    for (int nf = 0; nf < 4; nf++)
        #pragma unroll
        for (int r = 0; r < 4; r++) acc[nf][r] = 0.f;

    int ar = tid >> 2, ac = (tid & 3) * 8;
    int br = tid >> 1, bc = (tid & 1) * 16;
    const bf16* Abase = A  + (size_t)(bm + ar) * K + ac;
    const bf16* Bbase = Bt + (size_t)(bn + br) * K + bc;
    uint32_t sA = smem_u32(&As[0][ar][ac]);
    uint32_t sB = smem_u32(&Bs[0][br][bc]);
    uint32_t sA0 = smem_u32(&As[0][0][0]);
    uint32_t sB0 = smem_u32(&Bs[0][0][0]);
    const int ASS = 32 * 40 * 2, BSS = 64 * 40 * 2;

    uint32_t aBase = sA0 + (uint32_t)((wm * 16 + (lane & 15)) * 40 + (lane >> 4) * 8) * 2;
    uint32_t bBase = sB0 + (uint32_t)((wn * 32 + (lane & 7) + ((lane & 16) ? 8 : 0)) * 40
                                      + ((lane & 8) ? 8 : 0)) * 2;

    int nt = K / 32;
    #pragma unroll
    for (int s = 0; s < 2; s++) {
        cp16(sA + s * ASS, Abase + s * 32);
        cp16(sB + s * BSS, Bbase + s * 32);
        cp16(sB + s * BSS + 16, Bbase + s * 32 + 8);
        CP_COMMIT();
    }

    for (int i = 0; i < nt; i++) {
        if (i + 1 < nt) { CP_WAIT1(); } else { CP_WAIT0(); }
        __syncthreads();
        if (i + 2 < nt) {
            int s = (i + 2) % 3;
            cp16(sA + s * ASS, Abase + (i + 2) * 32);
            cp16(sB + s * BSS, Bbase + (i + 2) * 32);
            cp16(sB + s * BSS + 16, Bbase + (i + 2) * 32 + 8);
            CP_COMMIT();
        }
        int cb = i % 3;
        uint32_t aAddr = aBase + cb * ASS;
        uint32_t bAddr = bBase + cb * BSS;
        #pragma unroll
        for (int kk = 0; kk < 2; kk++) {
            uint32_t a[4], b01[4], b23[4];
            ldmatrix_x4(a[0], a[1], a[2], a[3], aAddr + kk * 32);
            ldmatrix_x4(b01[0], b01[1], b01[2], b01[3], bAddr + kk * 32);
            ldmatrix_x4(b23[0], b23[1], b23[2], b23[3], bAddr + 1280 + kk * 32);
            mma_bf16(acc[0], a, b01 + 0);
            mma_bf16(acc[1], a, b01 + 2);
            mma_bf16(acc[2], a, b23 + 0);
            mma_bf16(acc[3], a, b23 + 2);
        }
    }

    #pragma unroll
    for (int nf = 0; nf < 4; nf++) {
        int m = bm + wm * 16 + g;
        int n = bn + wn * 32 + nf * 8 + 2 * t;
        if (EPI == 5) {
            int c2 = n >> 1;
            float ab = bias[c2], gb = bias[FFI + c2];
            float a0 = acc[nf][0] + ab, g0 = acc[nf][1] + gb;
            float a1 = acc[nf][2] + ab, g1 = acc[nf][3] + gb;
            Cb[(size_t)m * (N / 2) + c2]       = __float2bfloat16(a0 * gelu_exact(g0));
            Cb[(size_t)(m + 8) * (N / 2) + c2] = __float2bfloat16(a1 * gelu_exact(g1));
            continue;
        }
        float b0 = bias ? bias[n] : 0.f;
        float b1 = bias ? bias[n + 1] : 0.f;
        float v0 = acc[nf][0] + b0;
        float v1 = acc[nf][1] + b1;
        float v2 = acc[nf][2] + b0;
        float v3 = acc[nf][3] + b1;
        if (EPI == 2) {
            C[(size_t)n * M + m]           = v0 + R[(size_t)n * M + m];
            C[(size_t)(n + 1) * M + m]     = v1 + R[(size_t)(n + 1) * M + m];
            C[(size_t)n * M + m + 8]       = v2 + R[(size_t)n * M + m + 8];
            C[(size_t)(n + 1) * M + m + 8] = v3 + R[(size_t)(n + 1) * M + m + 8];
        } else if (EPI == 3) {
            *(uint32_t*)&Cb[(size_t)m * N + n]       = bf2pk(v0, v1);
            *(uint32_t*)&Cb[(size_t)(m + 8) * N + n] = bf2pk(v2, v3);
        } else {
            if (EPI == 1 || EPI == 4) {
                float2 r0 = *(const float2*)&R[(size_t)m * N + n];
                float2 r1 = *(const float2*)&R[(size_t)(m + 8) * N + n];
                v0 += r0.x; v1 += r0.y; v2 += r1.x; v3 += r1.y;
            }
            *(float2*)&C[(size_t)m * N + n]       = make_float2(v0, v1);
            *(float2*)&C[(size_t)(m + 8) * N + n] = make_float2(v2, v3);
            if (EPI == 4) {
                *(uint32_t*)&Cb[(size_t)m * N + n]       = bf2pk(v0, v1);
                *(uint32_t*)&Cb[(size_t)(m + 8) * N + n] = bf2pk(v2, v3);
            }
        }
    }
}

// ---------------- bf16 flash self-attention, cp.async 2-stage, ldmatrix -------------
// grid (32, 8), 256 threads = 8 warps; warp w owns query rows [w*16, w*16+16)
__global__ void __launch_bounds__(256) flash_bf16_kernel(
    const bf16* __restrict__ QKV, bf16* __restrict__ O)
{
    __shared__ __align__(16) bf16 Ks[2][64][40];
    __shared__ __align__(16) bf16 Vs[2][64][40];
    __shared__ __align__(16) bf16 Ps[128][72];
    int h = blockIdx.y;
    int q0 = blockIdx.x * 128;
    int tid = threadIdx.x, wid = tid >> 5, lane = tid & 31;
    int g = lane >> 2, t = lane & 3;
    const float sclog = 0.15811388300841897f * LOG2E;

    uint32_t ksb = smem_u32(&Ks[0][0][0]);
    uint32_t vsb = smem_u32(&Vs[0][0][0]);
    uint32_t psb = smem_u32(&Ps[0][0]);
    const int KSS = 64 * 40 * 2, VSS = 64 * 40 * 2;

    uint32_t k16Base = (uint32_t)((lane & 7) + ((lane & 16) ? 8 : 0)) * 80
                       + ((lane & 8) ? 16 : 0);
    uint32_t k8Base  = (uint32_t)lane * 80 + 64;
    uint32_t pBase   = psb + (uint32_t)(wid * 16 + (lane & 15)) * 144 + (lane >> 4) * 16;

    uint32_t qa[2][4], qa2[2];
    {
        const bf16* qb = QKV + (size_t)(q0 + wid * 16) * 960 + h * 40;
        #pragma unroll
        for (int kk = 0; kk < 2; kk++) {
            int d = kk * 16 + 2 * t;
            qa[kk][0] = *(const uint32_t*)(qb + (size_t)g * 960 + d);
            qa[kk][1] = *(const uint32_t*)(qb + (size_t)(g + 8) * 960 + d);
            qa[kk][2] = *(const uint32_t*)(qb + (size_t)g * 960 + d + 8);
            qa[kk][3] = *(const uint32_t*)(qb + (size_t)(g + 8) * 960 + d + 8);
        }
        qa2[0] = *(const uint32_t*)(qb + (size_t)g * 960 + 32 + 2 * t);
        qa2[1] = *(const uint32_t*)(qb + (size_t)(g + 8) * 960 + 32 + 2 * t);
    }

    {
        for (int idx = tid; idx < 640; idx += 256) {
            int r = idx / 10, c = (idx % 10) * 4;
            cp8(ksb + r * 80 + c * 2, QKV + (size_t)r * 960 + 320 + h * 40 + c);
            cp8(vsb + r * 80 + c * 2, QKV + (size_t)r * 960 + 640 + h * 40 + c);
        }
        CP_COMMIT();
    }

    float o[5][4];
    #pragma unroll
    for (int nf = 0; nf < 5; nf++)
        #pragma unroll
        for (int r = 0; r < 4; r++) o[nf][r] = 0.f;
    float mA = -1e30f, mB = -1e30f, lA = 0.f, lB = 0.f;

    for (int it = 0; it < 64; it++) {
        int buf = it & 1;
        if (it < 63) {
            int k0 = (it + 1) * 64;
            uint32_t kd = ksb + (buf ^ 1) * KSS;
            uint32_t vd = vsb + (buf ^ 1) * VSS;
            for (int idx = tid; idx < 640; idx += 256) {
                int r = idx / 10, c = (idx % 10) * 4;
                cp8(kd + r * 80 + c * 2, QKV + (size_t)(k0 + r) * 960 + 320 + h * 40 + c);
                cp8(vd + r * 80 + c * 2, QKV + (size_t)(k0 + r) * 960 + 640 + h * 40 + c);
            }
            CP_COMMIT();
            CP_WAIT1();
        } else {
            CP_WAIT0();
        }
        __syncthreads();

        float s[8][4];
        #pragma unroll
        for (int nf = 0; nf < 8; nf++)
            #pragma unroll
            for (int r = 0; r < 4; r++) s[nf][r] = 0.f;
        uint32_t kbuf = ksb + buf * KSS;
        #pragma unroll
        for (int kk = 0; kk < 2; kk++) {
            #pragma unroll
            for (int nfp = 0; nfp < 4; nfp++) {
                uint32_t b4[4];
                ldmatrix_x4(b4[0], b4[1], b4[2], b4[3],
                            kbuf + k16Base + nfp * 1280 + kk * 32);
                mma_bf16(s[2 * nfp],     qa[kk], b4 + 0);
                mma_bf16(s[2 * nfp + 1], qa[kk], b4 + 2);
            }
        }
        #pragma unroll
        for (int half = 0; half < 2; half++) {
            uint32_t b4[4];
            ldmatrix_x4(b4[0], b4[1], b4[2], b4[3], kbuf + k8Base + half * 2560);
            mma_bf16_k8(s[half * 4 + 0], qa2, b4[0]);
            mma_bf16_k8(s[half * 4 + 1], qa2, b4[1]);
            mma_bf16_k8(s[half * 4 + 2], qa2, b4[2]);
            mma_bf16_k8(s[half * 4 + 3], qa2, b4[3]);
        }

        float mtA = mA, mtB = mB;
        #pragma unroll
        for (int nf = 0; nf < 8; nf++) {
            mtA = fmaxf(mtA, fmaxf(s[nf][0], s[nf][1]));
            mtB = fmaxf(mtB, fmaxf(s[nf][2], s[nf][3]));
        }
        mtA = fmaxf(mtA, __shfl_xor_sync(0xffffffffu, mtA, 1));
        mtA = fmaxf(mtA, __shfl_xor_sync(0xffffffffu, mtA, 2));
        mtB = fmaxf(mtB, __shfl_xor_sync(0xffffffffu, mtB, 1));
        mtB = fmaxf(mtB, __shfl_xor_sync(0xffffffffu, mtB, 2));
        float corrA = exp2f((mA - mtA) * sclog);
        float corrB = exp2f((mB - mtB) * sclog);
        mA = mtA; mB = mtB;
        lA *= corrA; lB *= corrB;
        #pragma unroll
        for (int nf = 0; nf < 5; nf++) {
            o[nf][0] *= corrA; o[nf][1] *= corrA;
            o[nf][2] *= corrB; o[nf][3] *= corrB;
        }
        int pr = wid * 16 + g;
        #pragma unroll
        for (int nf = 0; nf < 8; nf++) {
            float p0 = exp2f((s[nf][0] - mA) * sclog);
            float p1 = exp2f((s[nf][1] - mA) * sclog);
            float p2 = exp2f((s[nf][2] - mB) * sclog);
            float p3 = exp2f((s[nf][3] - mB) * sclog);
            lA += p0 + p1; lB += p2 + p3;
            *(uint32_t*)&Ps[pr][nf * 8 + 2 * t]     = bf2pk(p0, p1);
            *(uint32_t*)&Ps[pr + 8][nf * 8 + 2 * t] = bf2pk(p2, p3);
        }
        __syncwarp();

        uint32_t vbase = vsb + buf * VSS;
        #pragma unroll
        for (int kk = 0; kk < 4; kk++) {
            uint32_t pa[4];
            ldmatrix_x4(pa[0], pa[1], pa[2], pa[3], pBase + kk * 32);
            uint32_t rowaddr = vbase + (kk * 16 + (lane & 15)) * 80;
            #pragma unroll
            for (int nf = 0; nf < 5; nf++) {
                uint32_t bb[2];
                ldmatrix_x2_trans(bb[0], bb[1], rowaddr + nf * 16);
                mma_bf16(o[nf], pa, bb);
            }
        }
        __syncthreads();
    }

    lA += __shfl_xor_sync(0xffffffffu, lA, 1);
    lA += __shfl_xor_sync(0xffffffffu, lA, 2);
    lB += __shfl_xor_sync(0xffffffffu, lB, 1);
    lB += __shfl_xor_sync(0xffffffffu, lB, 2);
    float iA = 1.f / lA, iB = 1.f / lB;
    bf16* ob = O + (size_t)(q0 + wid * 16 + g) * D + h * 40;
    #pragma unroll
    for (int nf = 0; nf < 5; nf++) {
        *(uint32_t*)(ob + nf * 8 + 2 * t) = bf2pk(o[nf][0] * iA, o[nf][1] * iA);
        *(uint32_t*)(ob + (size_t)8 * D + nf * 8 + 2 * t) = bf2pk(o[nf][2] * iB, o[nf][3] * iB);
    }
}

// ---------------- cross attention (scalar; Q bf16, 77 keys; KV merged [96][640]) ----
__global__ void __launch_bounds__(128) cross_attn_kernel(
    const bf16* __restrict__ Q, const float* __restrict__ KV, bf16* __restrict__ O)
{
    const float scale = 0.15811388300841897f;
    int h = blockIdx.y;
    int qrow = blockIdx.x * 128 + threadIdx.x;
    int tid = threadIdx.x;

    __shared__ __align__(16) float Ks[CTX_N][40];
    __shared__ __align__(16) float Vs[CTX_N][40];
    for (int i = tid; i < CTX_N * 10; i += 128) {
        int r = i / 10, c = (i % 10) * 4;
        *(float4*)&Ks[r][c] = *(const float4*)(KV + (size_t)r * 640 + h * DH + c);
        *(float4*)&Vs[r][c] = *(const float4*)(KV + (size_t)r * 640 + 320 + h * DH + c);
    }
    __syncthreads();

    float4 q4[10], a4[10];
    const bf16* qp = Q + (size_t)qrow * D + h * DH;
    #pragma unroll
    for (int dd = 0; dd < 10; dd++) {
        __nv_bfloat162 b0 = *(const __nv_bfloat162*)(qp + dd * 4);
        __nv_bfloat162 b1 = *(const __nv_bfloat162*)(qp + dd * 4 + 2);
        q4[dd] = make_float4(__low2float(b0) * scale, __high2float(b0) * scale,
                             __low2float(b1) * scale, __high2float(b1) * scale);
        a4[dd] = make_float4(0.f, 0.f, 0.f, 0.f);
    }
    float m = -1e30f, l = 0.f;
    for (int j = 0; j < CTX_N; j++) {
        float s = 0.f;
        #pragma unroll
        for (int dd = 0; dd < 10; dd++) {
            float4 kk = *(const float4*)&Ks[j][dd * 4];
            s += q4[dd].x * kk.x + q4[dd].y * kk.y + q4[dd].z * kk.z + q4[dd].w * kk.w;
        }
        float mt = fmaxf(m, s);
        float corr = __expf(m - mt);
        float p = __expf(s - mt);
        m = mt;
        l = l * corr + p;
        #pragma unroll
        for (int dd = 0; dd < 10; dd++) {
            float4 vv = *(const float4*)&Vs[j][dd * 4];
            a4[dd].x = a4[dd].x * corr + p * vv.x;
            a4[dd].y = a4[dd].y * corr + p * vv.y;
            a4[dd].z = a4[dd].z * corr + p * vv.z;
            a4[dd].w = a4[dd].w * corr + p * vv.w;
        }
    }
    float inv = 1.f / l;
    bf16* op = O + (size_t)qrow * D + h * DH;
    #pragma unroll
    for (int dd = 0; dd < 10; dd++) {
        *(uint32_t*)(op + dd * 4)     = bf2pk(a4[dd].x * inv, a4[dd].y * inv);
        *(uint32_t*)(op + dd * 4 + 2) = bf2pk(a4[dd].z * inv, a4[dd].w * inv);
    }
}

// ---------------- launch ----------------
extern "C" void kernel_launch(void* const* d_in, const int* in_sizes, int n_in,
                              void* d_out, int out_size) {
    const float* x      = (const float*)d_in[0];
    const float* ctx    = (const float*)d_in[1];
    const float* gn_w   = (const float*)d_in[2];
    const float* gn_b   = (const float*)d_in[3];
    const float* pin_w  = (const float*)d_in[4];
    const float* pin_b  = (const float*)d_in[5];
    const float* ln1_w  = (const float*)d_in[6];
    const float* ln1_b  = (const float*)d_in[7];
    const float* q1     = (const float*)d_in[8];
    const float* k1     = (const float*)d_in[9];
    const float* v1     = (const float*)d_in[10];
    const float* o1_w   = (const float*)d_in[11];
    const float* o1_b   = (const float*)d_in[12];
    const float* ln2_w  = (const float*)d_in[13];
    const float* ln2_b  = (const float*)d_in[14];
    const float* q2     = (const float*)d_in[15];
    const float* k2     = (const float*)d_in[16];
    const float* v2     = (const float*)d_in[17];
    const float* o2_w   = (const float*)d_in[18];
    const float* o2_b   = (const float*)d_in[19];
    const float* ln3_w  = (const float*)d_in[20];
    const float* ln3_b  = (const float*)d_in[21];
    const float* ff1_w  = (const float*)d_in[22];
    const float* ff1_b  = (const float*)d_in[23];
    const float* ff2_w  = (const float*)d_in[24];
    const float* ff2_b  = (const float*)d_in[25];
    const float* pout_w = (const float*)d_in[26];
    const float* pout_b = (const float*)d_in[27];
    float* out = (float*)d_out;

    float *p_h, *p_h2, *p_kvc;
    bf16 *p_lnb, *p_qkvb, *p_attnb, *p_q2b, *p_h2b, *p_ffgb, *p_ctxb;
    bf16 *p_wqkv, *p_wo1, *p_wq2, *p_wo2, *p_wff1, *p_wff2, *p_wpin, *p_wpout, *p_wkv2;
    cudaGetSymbolAddress((void**)&p_h,    g_h);
    cudaGetSymbolAddress((void**)&p_h2,   g_h2);
    cudaGetSymbolAddress((void**)&p_kvc,  g_kvc);
    cudaGetSymbolAddress((void**)&p_lnb,  g_lnb);
    cudaGetSymbolAddress((void**)&p_qkvb, g_qkvb);
    cudaGetSymbolAddress((void**)&p_attnb,g_attnb);
    cudaGetSymbolAddress((void**)&p_q2b,  g_q2b);
    cudaGetSymbolAddress((void**)&p_h2b,  g_h2b);
    cudaGetSymbolAddress((void**)&p_ffgb, g_ffgb);
    cudaGetSymbolAddress((void**)&p_ctxb, g_ctxb);
    cudaGetSymbolAddress((void**)&p_wqkv, g_wqkv);
    cudaGetSymbolAddress((void**)&p_wo1,  g_wo1);
    cudaGetSymbolAddress((void**)&p_wq2,  g_wq2);
    cudaGetSymbolAddress((void**)&p_wo2,  g_wo2);
    cudaGetSymbolAddress((void**)&p_wff1, g_wff1);
    cudaGetSymbolAddress((void**)&p_wff2, g_wff2);
    cudaGetSymbolAddress((void**)&p_wpin, g_wpin);
    cudaGetSymbolAddress((void**)&p_wpout,g_wpout);
    cudaGetSymbolAddress((void**)&p_wkv2, g_wkv2);

    dim3 gD(D / 64, N_TOK / 32);            // (5, 128)

    // weight prep (+ ctx conversion) + GroupNorm
    prep_weights_kernel<<<2768, 256>>>(q1, k1, v1, o1_w, q2, o2_w, ff1_w, ff2_w,
                                       pin_w, pout_w, k2, v2, ctx);
    gn_stats_kernel<<<GROUPS, 256>>>(x);
    gn_apply_t_kernel<<<dim3(32, 10), 256>>>(x, gn_w, gn_b, p_lnb);
    gemm_bf16_kernel<0><<<gD, 128>>>(p_lnb, p_wpin, pin_b, nullptr, p_h, nullptr, N_TOK, D, D);

    // self-attention
    layernorm_kernel<<<N_TOK / 8, 256>>>(p_h, ln1_w, ln1_b, p_lnb);
    gemm_bf16_kernel<3><<<dim3(3 * D / 64, N_TOK / 32), 128>>>(p_lnb, p_wqkv, nullptr, nullptr, nullptr, p_qkvb, N_TOK, 3 * D, D);
    flash_bf16_kernel<<<dim3(N_TOK / 128, HEADS), 256>>>(p_qkvb, p_attnb);
    gemm_bf16_kernel<1><<<gD, 128>>>(p_attnb, p_wo1, o1_b, p_h, p_h2, nullptr, N_TOK, D, D);

    // cross-attention
    layernorm_kernel<<<N_TOK / 8, 256>>>(p_h2, ln2_w, ln2_b, p_lnb);
    gemm_bf16_kernel<3><<<gD, 128>>>(p_lnb, p_wq2, nullptr, nullptr, nullptr, p_q2b, N_TOK, D, D);
    gemm_bf16_kernel<0><<<dim3(2 * D / 64, CTX_M / 32), 128>>>(p_ctxb, p_wkv2, nullptr, nullptr, p_kvc, nullptr, CTX_M, 2 * D, CTX_D);
    cross_attn_kernel<<<dim3(N_TOK / 128, HEADS), 128>>>(p_q2b, p_kvc, p_attnb);
    gemm_bf16_kernel<1><<<gD, 128>>>(p_attnb, p_wo2, o2_b, p_h2, p_h, nullptr, N_TOK, D, D);

    // GEGLU FF (fused into ff1 epilogue via interleaved weights)
    layernorm_kernel<<<N_TOK / 8, 256>>>(p_h, ln3_w, ln3_b, p_lnb);
    gemm_bf16_kernel<5><<<dim3(2 * FFI / 64, N_TOK / 32), 128>>>(p_lnb, p_wff1, ff1_b, nullptr, nullptr, p_ffgb, N_TOK, 2 * FFI, D);
    gemm_bf16_kernel<4><<<gD, 128>>>(p_ffgb, p_wff2, ff2_b, p_h, p_h2, p_h2b, N_TOK, D, FFI);

    // proj_out + residual (transposed store back to [C][HW])
    gemm_bf16_kernel<2><<<gD, 128>>>(p_h2b, p_wpout, pout_b, x, out, nullptr, N_TOK, D, D);
}